// round 1
// baseline (speedup 1.0000x reference)
#include <cuda_runtime.h>
#include <cuda_bf16.h>
#include <cstdint>

// Problem constants (fixed for this dataset)
#define BB 64
#define NN 1024
#define DD 1024

// Scratch (device globals; no allocations allowed)
__device__ float g_qh[BB * DD];       // h_t @ W_h^T
__device__ float g_scores[BB * NN];   // pre-softmax scores

__device__ __forceinline__ float tanh_fast(float x) {
    float y;
    asm("tanh.approx.f32 %0, %1;" : "=f"(y) : "f"(x));
    return y;
}

// ---------------------------------------------------------------------------
// Kernel A: qh[b,e] = sum_d h[b,d] * Wh[e,d]
// grid (B, D/8), block 256 (8 warps, warp per output e)
// ---------------------------------------------------------------------------
__global__ void qh_kernel(const float* __restrict__ h,
                          const float* __restrict__ Wh) {
    int b = blockIdx.x;
    int e = blockIdx.y * 8 + (threadIdx.x >> 5);
    int lane = threadIdx.x & 31;

    const float4* hr = reinterpret_cast<const float4*>(h + (size_t)b * DD);
    const float4* wr = reinterpret_cast<const float4*>(Wh + (size_t)e * DD);

    float acc = 0.f;
#pragma unroll
    for (int i = 0; i < DD / 4 / 32; i++) {
        float4 a = hr[lane + i * 32];
        float4 w = wr[lane + i * 32];
        acc += a.x * w.x + a.y * w.y + a.z * w.z + a.w * w.w;
    }
#pragma unroll
    for (int off = 16; off > 0; off >>= 1)
        acc += __shfl_xor_sync(0xffffffffu, acc, off);
    if (lane == 0) g_qh[b * DD + e] = acc;
}

// ---------------------------------------------------------------------------
// Kernel B: fused scores.
//   scores[b,n] = sum_e v[e] * tanh(qh[b,e] + sum_d keys[b,n,d]*Wk[e,d])
// grid (B, N/128), block 256. Per CTA: 128 n-rows; loops 8 e-tiles of 128,
// each a 128x128x1024 register-tiled sgemm consumed in-register.
// ---------------------------------------------------------------------------
#define KT 16
#define LDS_PAD 132

__global__ __launch_bounds__(256, 2)
void scores_kernel(const float* __restrict__ keys,
                   const float* __restrict__ Wk,
                   const float* __restrict__ v) {
    __shared__ float As[KT][LDS_PAD];   // keys tile   [d][n-row]
    __shared__ float Bs[KT][LDS_PAD];   // Wk tile     [d][e-row]
    __shared__ float qs[128];
    __shared__ float vs[128];

    const int b  = blockIdx.x;
    const int n0 = blockIdx.y * 128;
    const int tid = threadIdx.x;
    const int tx = tid & 15;
    const int ty = tid >> 4;

    const int r0 = ty * 4, r1 = r0 + 64;   // n rows handled by thread
    const int c0 = tx * 4, c1 = c0 + 64;   // e cols handled by thread

    // staging indices for global->smem
    const int lr = tid >> 2;          // row 0..63 (and +64)
    const int lc = (tid & 3) * 4;     // d sub-offset 0,4,8,12

    const float* keyb = keys + (size_t)b * NN * DD;

    float sacc[8];
#pragma unroll
    for (int i = 0; i < 8; i++) sacc[i] = 0.f;

    for (int e0 = 0; e0 < DD; e0 += 128) {
        __syncthreads();   // prior epilogue reads of qs/vs done
        if (tid < 128) {
            qs[tid] = g_qh[b * DD + e0 + tid];
            vs[tid] = v[e0 + tid];
        }

        float C[8][8];
#pragma unroll
        for (int i = 0; i < 8; i++)
#pragma unroll
            for (int j = 0; j < 8; j++) C[i][j] = 0.f;

        for (int d0 = 0; d0 < DD; d0 += KT) {
            float4 a0 = *reinterpret_cast<const float4*>(
                &keyb[(size_t)(n0 + lr) * DD + d0 + lc]);
            float4 a1 = *reinterpret_cast<const float4*>(
                &keyb[(size_t)(n0 + lr + 64) * DD + d0 + lc]);
            float4 b0 = *reinterpret_cast<const float4*>(
                &Wk[(size_t)(e0 + lr) * DD + d0 + lc]);
            float4 b1 = *reinterpret_cast<const float4*>(
                &Wk[(size_t)(e0 + lr + 64) * DD + d0 + lc]);

            __syncthreads();   // previous tile fully consumed
            As[lc + 0][lr] = a0.x; As[lc + 1][lr] = a0.y;
            As[lc + 2][lr] = a0.z; As[lc + 3][lr] = a0.w;
            As[lc + 0][lr + 64] = a1.x; As[lc + 1][lr + 64] = a1.y;
            As[lc + 2][lr + 64] = a1.z; As[lc + 3][lr + 64] = a1.w;
            Bs[lc + 0][lr] = b0.x; Bs[lc + 1][lr] = b0.y;
            Bs[lc + 2][lr] = b0.z; Bs[lc + 3][lr] = b0.w;
            Bs[lc + 0][lr + 64] = b1.x; Bs[lc + 1][lr + 64] = b1.y;
            Bs[lc + 2][lr + 64] = b1.z; Bs[lc + 3][lr + 64] = b1.w;
            __syncthreads();

#pragma unroll
            for (int kk = 0; kk < KT; kk++) {
                float4 A0 = *reinterpret_cast<const float4*>(&As[kk][r0]);
                float4 A1 = *reinterpret_cast<const float4*>(&As[kk][r1]);
                float4 B0 = *reinterpret_cast<const float4*>(&Bs[kk][c0]);
                float4 B1 = *reinterpret_cast<const float4*>(&Bs[kk][c1]);
                float ar[8] = {A0.x, A0.y, A0.z, A0.w, A1.x, A1.y, A1.z, A1.w};
                float br[8] = {B0.x, B0.y, B0.z, B0.w, B1.x, B1.y, B1.z, B1.w};
#pragma unroll
                for (int i = 0; i < 8; i++)
#pragma unroll
                    for (int j = 0; j < 8; j++)
                        C[i][j] += ar[i] * br[j];
            }
        }
        __syncthreads();   // make qs/vs visible (also separates from smem use)

        // consume tile: sacc[i] += sum_j v[e]*tanh(qh[e] + C[i][j])
#pragma unroll
        for (int j = 0; j < 8; j++) {
            int col = (j < 4) ? (c0 + j) : (c1 + j - 4);
            float qv = qs[col];
            float vv = vs[col];
#pragma unroll
            for (int i = 0; i < 8; i++)
                sacc[i] += vv * tanh_fast(qv + C[i][j]);
        }
    }

    // reduce over tx (16 lanes within each half-warp)
#pragma unroll
    for (int i = 0; i < 8; i++) {
        float s = sacc[i];
        s += __shfl_xor_sync(0xffffffffu, s, 1);
        s += __shfl_xor_sync(0xffffffffu, s, 2);
        s += __shfl_xor_sync(0xffffffffu, s, 4);
        s += __shfl_xor_sync(0xffffffffu, s, 8);
        sacc[i] = s;
    }
    if (tx == 0) {
#pragma unroll
        for (int i = 0; i < 8; i++) {
            int n = n0 + ((i < 4) ? (r0 + i) : (r1 + i - 4));
            g_scores[b * NN + n] = sacc[i];
        }
    }
}

// ---------------------------------------------------------------------------
// Kernel C: softmax over N per row; writes alpha into d_out[B*D ...]
// grid (B), block 256
// ---------------------------------------------------------------------------
__global__ void softmax_kernel(float* __restrict__ out) {
    __shared__ float sx[NN];
    __shared__ float red[256];
    const int b = blockIdx.x;
    const int tid = threadIdx.x;
    const float* s = &g_scores[b * NN];

    float m = -1e30f;
    for (int i = tid; i < NN; i += 256) {
        float val = s[i];
        sx[i] = val;
        m = fmaxf(m, val);
    }
    red[tid] = m;
    __syncthreads();
    for (int off = 128; off > 0; off >>= 1) {
        if (tid < off) red[tid] = fmaxf(red[tid], red[tid + off]);
        __syncthreads();
    }
    const float M = red[0];
    __syncthreads();

    float sum = 0.f;
    for (int i = tid; i < NN; i += 256) {
        float e = __expf(sx[i] - M);
        sx[i] = e;
        sum += e;
    }
    red[tid] = sum;
    __syncthreads();
    for (int off = 128; off > 0; off >>= 1) {
        if (tid < off) red[tid] += red[tid + off];
        __syncthreads();
    }
    const float inv = 1.f / red[0];
    __syncthreads();

    float* alpha = out + (size_t)BB * DD + (size_t)b * NN;
    for (int i = tid; i < NN; i += 256)
        alpha[i] = sx[i] * inv;
}

// ---------------------------------------------------------------------------
// Kernel D: context[b,d] = sum_n alpha[b,n] * keys[b,n,d]
// grid (B, D/256), block 256, thread per d. Deterministic (no atomics).
// ---------------------------------------------------------------------------
__global__ void context_kernel(const float* __restrict__ keys,
                               float* __restrict__ out) {
    __shared__ float al[NN];
    const int b = blockIdx.x;
    const int d = blockIdx.y * 256 + threadIdx.x;
    const float* alpha = out + (size_t)BB * DD + (size_t)b * NN;
    for (int i = threadIdx.x; i < NN; i += 256) al[i] = alpha[i];
    __syncthreads();

    const float* kb = keys + (size_t)b * NN * DD + d;
    float acc = 0.f;
#pragma unroll 8
    for (int n = 0; n < NN; n++)
        acc += al[n] * kb[(size_t)n * DD];
    out[(size_t)b * DD + d] = acc;
}

// ---------------------------------------------------------------------------
extern "C" void kernel_launch(void* const* d_in, const int* in_sizes, int n_in,
                              void* d_out, int out_size) {
    const float* h_t  = (const float*)d_in[0];
    const float* keys = (const float*)d_in[1];
    const float* W_h  = (const float*)d_in[2];
    const float* W_k  = (const float*)d_in[3];
    const float* v    = (const float*)d_in[4];
    float* out = (float*)d_out;

    qh_kernel<<<dim3(BB, DD / 8), 256>>>(h_t, W_h);
    scores_kernel<<<dim3(BB, NN / 128), 256>>>(keys, W_k, v);
    softmax_kernel<<<BB, 256>>>(out);
    context_kernel<<<dim3(BB, DD / 256), 256>>>(keys, out);
}

// round 5
// speedup vs baseline: 1.9739x; 1.9739x over previous
#include <cuda_runtime.h>
#include <cuda_fp16.h>
#include <cstdint>

#define BB 64
#define NN 1024
#define DD 1024

// ---------------- device scratch (no allocations allowed) -------------------
__device__ float g_qh[BB * DD];
__device__ float g_scores[BB * NN];
__device__ __half g_keys_hi[(size_t)BB * NN * DD];
__device__ __half g_keys_lo[(size_t)BB * NN * DD];
__device__ __half g_wk_hi[DD * DD];
__device__ __half g_wk_lo[DD * DD];

__device__ __forceinline__ uint32_t smem_u32(const void* p) {
    uint32_t a;
    asm("{ .reg .u64 t; cvta.to.shared.u64 t, %1; cvt.u32.u64 %0, t; }"
        : "=r"(a) : "l"(p));
    return a;
}

__device__ __forceinline__ float tanh_fast(float x) {
    float y;
    asm("tanh.approx.f32 %0, %1;" : "=f"(y) : "f"(x));
    return y;
}

__device__ __forceinline__ void ldsm4(uint32_t* r, uint32_t addr) {
    asm volatile("ldmatrix.sync.aligned.m8n8.x4.shared.b16 {%0,%1,%2,%3}, [%4];"
                 : "=r"(r[0]), "=r"(r[1]), "=r"(r[2]), "=r"(r[3])
                 : "r"(addr));
}

__device__ __forceinline__ void hmma(float* c, const uint32_t* a,
                                     uint32_t b0, uint32_t b1) {
    asm volatile(
        "mma.sync.aligned.m16n8k16.row.col.f32.f16.f16.f32 "
        "{%0,%1,%2,%3}, {%4,%5,%6,%7}, {%8,%9}, {%0,%1,%2,%3};"
        : "+f"(c[0]), "+f"(c[1]), "+f"(c[2]), "+f"(c[3])
        : "r"(a[0]), "r"(a[1]), "r"(a[2]), "r"(a[3]), "r"(b0), "r"(b1));
}

__device__ __forceinline__ void cp_async16(uint32_t dst, const void* src) {
    asm volatile("cp.async.cg.shared.global [%0], [%1], 16;"
                 :: "r"(dst), "l"(src));
}
__device__ __forceinline__ void cp_commit() {
    asm volatile("cp.async.commit_group;");
}
template <int N>
__device__ __forceinline__ void cp_wait() {
    asm volatile("cp.async.wait_group %0;" :: "n"(N));
}

// ---------------------------------------------------------------------------
// split: f32 -> fp16 hi + fp16 lo   (one float4 per thread)
// ---------------------------------------------------------------------------
__global__ void split_kernel(const float* __restrict__ src,
                             __half* __restrict__ hi,
                             __half* __restrict__ lo) {
    size_t i = (size_t)blockIdx.x * 256 + threadIdx.x;
    float4 x = reinterpret_cast<const float4*>(src)[i];
    float f[4] = {x.x, x.y, x.z, x.w};
    __half h[4], l[4];
#pragma unroll
    for (int k = 0; k < 4; k++) {
        h[k] = __float2half(f[k]);
        l[k] = __float2half(f[k] - __half2float(h[k]));
    }
    reinterpret_cast<uint2*>(hi)[i] = *reinterpret_cast<uint2*>(h);
    reinterpret_cast<uint2*>(lo)[i] = *reinterpret_cast<uint2*>(l);
}

// ---------------------------------------------------------------------------
// qh[b,e] = sum_d h[b,d] * Wh[e,d]  (fp32, tiny)
// ---------------------------------------------------------------------------
__global__ void qh_kernel(const float* __restrict__ h,
                          const float* __restrict__ Wh) {
    int b = blockIdx.x;
    int e = blockIdx.y * 8 + (threadIdx.x >> 5);
    int lane = threadIdx.x & 31;
    const float4* hr = reinterpret_cast<const float4*>(h + (size_t)b * DD);
    const float4* wr = reinterpret_cast<const float4*>(Wh + (size_t)e * DD);
    float acc = 0.f;
#pragma unroll
    for (int i = 0; i < DD / 4 / 32; i++) {
        float4 a = hr[lane + i * 32];
        float4 w = wr[lane + i * 32];
        acc += a.x * w.x + a.y * w.y + a.z * w.z + a.w * w.w;
    }
#pragma unroll
    for (int off = 16; off > 0; off >>= 1)
        acc += __shfl_xor_sync(0xffffffffu, acc, off);
    if (lane == 0) g_qh[b * DD + e] = acc;
}

// ---------------------------------------------------------------------------
// Fused scores kernel (HMMA mma.sync).
// CTA = (b, 128-n tile). 8 e-passes of 128. Per pass: GEMM over K=3072
// (3 segments: Ah*Bh, Ah*Bl, Al*Bh), k-chunks of 64, cp.async double buffer.
// Warp tile 32(n) x 64(e); epilogue sacc += v*tanh(qh + C) in registers.
// ---------------------------------------------------------------------------
#define SA 72                    // smem stride in halves (64 + 8 pad)
#define TILE_B (128 * SA * 2)    // 18432 bytes per 128x64 tile
#define OFF_QS (4 * TILE_B)      // 73728
#define OFF_VS (OFF_QS + 512)
#define OFF_RED (OFF_VS + 512)
#define SMEM_TOTAL (OFF_RED + 1024)

struct Stage {
    uint32_t dstA, dstB;
    const __half *srcA, *srcB;
};

__device__ __forceinline__ void stage_chunk(const Stage& s, int tid) {
#pragma unroll
    for (int it = 0; it < 4; it++) {
        int idx = tid + it * 256;
        int row = idx >> 3, c8 = idx & 7;
        cp_async16(s.dstA + (uint32_t)(row * SA + c8 * 8) * 2,
                   s.srcA + (size_t)row * DD + c8 * 8);
    }
#pragma unroll
    for (int it = 0; it < 4; it++) {
        int idx = tid + it * 256;
        int row = idx >> 3, c8 = idx & 7;
        cp_async16(s.dstB + (uint32_t)(row * SA + c8 * 8) * 2,
                   s.srcB + (size_t)row * DD + c8 * 8);
    }
}

__global__ __launch_bounds__(256, 2)
void scores_mma_kernel(const float* __restrict__ v) {
    extern __shared__ char sm[];
    const uint32_t sbase = smem_u32(sm);
    const int tid = threadIdx.x;
    const int wid = tid >> 5;
    const int lane = tid & 31;
    const int b = blockIdx.x;
    const int n0 = blockIdx.y * 128;

    const int wn = wid & 3;   // n-warp (0..3), 32 rows each
    const int we = wid >> 2;  // e-warp (0..1), 64 cols each

    float* qs = reinterpret_cast<float*>(sm + OFF_QS);
    float* vs = reinterpret_cast<float*>(sm + OFF_VS);
    float* red = reinterpret_cast<float*>(sm + OFF_RED);

    const __half* khi = g_keys_hi + ((size_t)b * NN + n0) * DD;
    const __half* klo = g_keys_lo + ((size_t)b * NN + n0) * DD;

    // ldmatrix lane addressing (in half units)
    const int a_row = lane & 15;
    const int a_col = (lane >> 4) << 3;
    const int b_g = lane & 7;
    const int b_sel = lane >> 3;
    const int b_row = b_g + ((b_sel >> 1) << 3);
    const int b_col = (b_sel & 1) << 3;

    float C[2][8][4];
#pragma unroll
    for (int m = 0; m < 2; m++)
#pragma unroll
        for (int nf = 0; nf < 8; nf++)
#pragma unroll
            for (int r = 0; r < 4; r++) C[m][nf][r] = 0.f;
    float sacc[4] = {0.f, 0.f, 0.f, 0.f};

    for (int ep = 0; ep < 8; ep++) {
        const int e0 = ep * 128;
        if (tid < 128) {
            qs[tid] = g_qh[b * DD + e0 + tid];
            vs[tid] = v[e0 + tid];
        }

        // chunk c (0..47): seg = c>>4, k0 = (c&15)*64
        auto mk = [&](int c) -> Stage {
            int seg = c >> 4;
            int k0 = (c & 15) * 64;
            int buf = c & 1;
            Stage s;
            s.dstA = sbase + buf * 2 * TILE_B;
            s.dstB = s.dstA + TILE_B;
            s.srcA = (seg == 2 ? klo : khi) + k0;
            const __half* wbase = (seg == 1 ? g_wk_lo : g_wk_hi);
            s.srcB = wbase + (size_t)e0 * DD + k0;
            return s;
        };

        stage_chunk(mk(0), tid);
        cp_commit();

        for (int c = 0; c < 48; c++) {
            if (c < 47) {
                stage_chunk(mk(c + 1), tid);
                cp_commit();
                cp_wait<1>();
            } else {
                cp_wait<0>();
            }
            __syncthreads();

            const uint32_t bufA = sbase + (uint32_t)(c & 1) * 2 * TILE_B;
            const uint32_t bufB = bufA + TILE_B;

#pragma unroll
            for (int kk = 0; kk < 4; kk++) {
                uint32_t a[2][4];
#pragma unroll
                for (int m = 0; m < 2; m++) {
                    uint32_t ad = bufA +
                        (uint32_t)((wn * 32 + m * 16 + a_row) * SA +
                                   kk * 16 + a_col) * 2;
                    ldsm4(a[m], ad);
                }
                uint32_t bf[4][4];
#pragma unroll
                for (int q = 0; q < 4; q++) {
                    uint32_t bd = bufB +
                        (uint32_t)((we * 64 + q * 16 + b_row) * SA +
                                   kk * 16 + b_col) * 2;
                    ldsm4(bf[q], bd);
                }
#pragma unroll
                for (int m = 0; m < 2; m++)
#pragma unroll
                    for (int nf = 0; nf < 8; nf++)
                        hmma(C[m][nf], a[m],
                             bf[nf >> 1][(nf & 1) * 2],
                             bf[nf >> 1][(nf & 1) * 2 + 1]);
            }
            __syncthreads();
        }

        // epilogue: sacc += v * tanh(qh + C); zero C for next pass
#pragma unroll
        for (int m = 0; m < 2; m++)
#pragma unroll
            for (int nf = 0; nf < 8; nf++) {
                float* c = C[m][nf];
                int ec = we * 64 + nf * 8 + ((lane & 3) << 1);
                float q0 = qs[ec], q1 = qs[ec + 1];
                float v0 = vs[ec], v1 = vs[ec + 1];
                sacc[m * 2 + 0] += v0 * tanh_fast(q0 + c[0]) +
                                   v1 * tanh_fast(q1 + c[1]);
                sacc[m * 2 + 1] += v0 * tanh_fast(q0 + c[2]) +
                                   v1 * tanh_fast(q1 + c[3]);
                c[0] = c[1] = c[2] = c[3] = 0.f;
            }
        __syncthreads();   // qs/vs safe to overwrite next pass
    }

    // reduce sacc over the 4-lane k-groups (same rows)
#pragma unroll
    for (int i = 0; i < 4; i++) {
        sacc[i] += __shfl_xor_sync(0xffffffffu, sacc[i], 1);
        sacc[i] += __shfl_xor_sync(0xffffffffu, sacc[i], 2);
    }
    if ((lane & 3) == 0) {
        int g = lane >> 2;
        float* r = red + we * 128 + wn * 32;
        r[g]      = sacc[0];
        r[g + 8]  = sacc[1];
        r[g + 16] = sacc[2];
        r[g + 24] = sacc[3];
    }
    __syncthreads();
    if (tid < 128)
        g_scores[b * NN + n0 + tid] = red[tid] + red[128 + tid];
}

// ---------------------------------------------------------------------------
// softmax over N per row; writes alpha into d_out[B*D ...]
// ---------------------------------------------------------------------------
__global__ void softmax_kernel(float* __restrict__ out) {
    __shared__ float sx[NN];
    __shared__ float red[256];
    const int b = blockIdx.x;
    const int tid = threadIdx.x;
    const float* s = &g_scores[b * NN];

    float m = -1e30f;
    for (int i = tid; i < NN; i += 256) {
        float val = s[i];
        sx[i] = val;
        m = fmaxf(m, val);
    }
    red[tid] = m;
    __syncthreads();
    for (int off = 128; off > 0; off >>= 1) {
        if (tid < off) red[tid] = fmaxf(red[tid], red[tid + off]);
        __syncthreads();
    }
    const float M = red[0];
    __syncthreads();

    float sum = 0.f;
    for (int i = tid; i < NN; i += 256) {
        float e = __expf(sx[i] - M);
        sx[i] = e;
        sum += e;
    }
    red[tid] = sum;
    __syncthreads();
    for (int off = 128; off > 0; off >>= 1) {
        if (tid < off) red[tid] += red[tid + off];
        __syncthreads();
    }
    const float inv = 1.f / red[0];
    __syncthreads();

    float* alpha = out + (size_t)BB * DD + (size_t)b * NN;
    for (int i = tid; i < NN; i += 256)
        alpha[i] = sx[i] * inv;
}

// ---------------------------------------------------------------------------
// context[b,d] = sum_n alpha[b,n] * keys[b,n,d] — float4 per thread
// ---------------------------------------------------------------------------
__global__ void context_kernel(const float* __restrict__ keys,
                               float* __restrict__ out) {
    __shared__ float al[NN];
    const int b = blockIdx.x;
    const int t = threadIdx.x;
    const float* alpha = out + (size_t)BB * DD + (size_t)b * NN;
    for (int i = t; i < NN; i += 256) al[i] = alpha[i];
    __syncthreads();

    const float4* kb = reinterpret_cast<const float4*>(
        keys + (size_t)b * NN * DD) + t;
    float4 acc = make_float4(0.f, 0.f, 0.f, 0.f);
#pragma unroll 8
    for (int n = 0; n < NN; n++) {
        float a = al[n];
        float4 kv = kb[(size_t)n * (DD / 4)];
        acc.x += a * kv.x;
        acc.y += a * kv.y;
        acc.z += a * kv.z;
        acc.w += a * kv.w;
    }
    reinterpret_cast<float4*>(out + (size_t)b * DD)[t] = acc;
}

// ---------------------------------------------------------------------------
extern "C" void kernel_launch(void* const* d_in, const int* in_sizes, int n_in,
                              void* d_out, int out_size) {
    const float* h_t  = (const float*)d_in[0];
    const float* keys = (const float*)d_in[1];
    const float* W_h  = (const float*)d_in[2];
    const float* W_k  = (const float*)d_in[3];
    const float* v    = (const float*)d_in[4];
    float* out = (float*)d_out;

    cudaFuncSetAttribute(scores_mma_kernel,
                         cudaFuncAttributeMaxDynamicSharedMemorySize, SMEM_TOTAL);

    __half *khi, *klo, *whi, *wlo;
    cudaGetSymbolAddress((void**)&khi, g_keys_hi);
    cudaGetSymbolAddress((void**)&klo, g_keys_lo);
    cudaGetSymbolAddress((void**)&whi, g_wk_hi);
    cudaGetSymbolAddress((void**)&wlo, g_wk_lo);

    split_kernel<<<(size_t)BB * NN * DD / 4 / 256, 256>>>(keys, khi, klo);
    split_kernel<<<DD * DD / 4 / 256, 256>>>(W_k, whi, wlo);
    qh_kernel<<<dim3(BB, DD / 8), 256>>>(h_t, W_h);
    scores_mma_kernel<<<dim3(BB, 8), 256, SMEM_TOTAL>>>(v);
    softmax_kernel<<<BB, 256>>>(out);
    context_kernel<<<BB, 256>>>(keys, out);
}

// round 6
// speedup vs baseline: 3.8911x; 1.9712x over previous
#include <cuda_runtime.h>
#include <cuda_fp16.h>
#include <cstdint>

#define BB 64
#define NN 1024
#define DD 1024

// ---------------- device scratch (no allocations allowed) -------------------
__device__ float g_qh[BB * DD];
__device__ float g_scores[BB * NN];
__device__ __half g_keys_hi[(size_t)BB * NN * DD];
__device__ __half g_wk_hi[DD * DD];
__device__ __half g_wk_lo[DD * DD];

__device__ __forceinline__ uint32_t smem_u32(const void* p) {
    uint32_t a;
    asm("{ .reg .u64 t; cvta.to.shared.u64 t, %1; cvt.u32.u64 %0, t; }"
        : "=r"(a) : "l"(p));
    return a;
}

__device__ __forceinline__ float tanh_fast(float x) {
    float y;
    asm("tanh.approx.f32 %0, %1;" : "=f"(y) : "f"(x));
    return y;
}

__device__ __forceinline__ void ldsm4(uint32_t* r, uint32_t addr) {
    asm volatile("ldmatrix.sync.aligned.m8n8.x4.shared.b16 {%0,%1,%2,%3}, [%4];"
                 : "=r"(r[0]), "=r"(r[1]), "=r"(r[2]), "=r"(r[3])
                 : "r"(addr));
}

__device__ __forceinline__ void hmma(float* c, const uint32_t* a,
                                     uint32_t b0, uint32_t b1) {
    asm volatile(
        "mma.sync.aligned.m16n8k16.row.col.f32.f16.f16.f32 "
        "{%0,%1,%2,%3}, {%4,%5,%6,%7}, {%8,%9}, {%0,%1,%2,%3};"
        : "+f"(c[0]), "+f"(c[1]), "+f"(c[2]), "+f"(c[3])
        : "r"(a[0]), "r"(a[1]), "r"(a[2]), "r"(a[3]), "r"(b0), "r"(b1));
}

__device__ __forceinline__ void cp_async16(uint32_t dst, const void* src) {
    asm volatile("cp.async.cg.shared.global [%0], [%1], 16;"
                 :: "r"(dst), "l"(src));
}
__device__ __forceinline__ void cp_commit() {
    asm volatile("cp.async.commit_group;");
}
template <int N>
__device__ __forceinline__ void cp_wait() {
    asm volatile("cp.async.wait_group %0;" :: "n"(N));
}

// ---------------------------------------------------------------------------
// splits: f32 -> fp16 hi (+ optional lo)
// ---------------------------------------------------------------------------
__global__ void split1_kernel(const float* __restrict__ src,
                              __half* __restrict__ hi) {
    size_t i = (size_t)blockIdx.x * 256 + threadIdx.x;
    float4 x = reinterpret_cast<const float4*>(src)[i];
    float f[4] = {x.x, x.y, x.z, x.w};
    __half h[4];
#pragma unroll
    for (int k = 0; k < 4; k++) h[k] = __float2half(f[k]);
    reinterpret_cast<uint2*>(hi)[i] = *reinterpret_cast<uint2*>(h);
}

__global__ void split2_kernel(const float* __restrict__ src,
                              __half* __restrict__ hi,
                              __half* __restrict__ lo) {
    size_t i = (size_t)blockIdx.x * 256 + threadIdx.x;
    float4 x = reinterpret_cast<const float4*>(src)[i];
    float f[4] = {x.x, x.y, x.z, x.w};
    __half h[4], l[4];
#pragma unroll
    for (int k = 0; k < 4; k++) {
        h[k] = __float2half(f[k]);
        l[k] = __float2half(f[k] - __half2float(h[k]));
    }
    reinterpret_cast<uint2*>(hi)[i] = *reinterpret_cast<uint2*>(h);
    reinterpret_cast<uint2*>(lo)[i] = *reinterpret_cast<uint2*>(l);
}

// ---------------------------------------------------------------------------
// qh[b,e] = sum_d h[b,d] * Wh[e,d]  (fp32, tiny)
// ---------------------------------------------------------------------------
__global__ void qh_kernel(const float* __restrict__ h,
                          const float* __restrict__ Wh) {
    int b = blockIdx.x;
    int e = blockIdx.y * 8 + (threadIdx.x >> 5);
    int lane = threadIdx.x & 31;
    const float4* hr = reinterpret_cast<const float4*>(h + (size_t)b * DD);
    const float4* wr = reinterpret_cast<const float4*>(Wh + (size_t)e * DD);
    float acc = 0.f;
#pragma unroll
    for (int i = 0; i < DD / 4 / 32; i++) {
        float4 a = hr[lane + i * 32];
        float4 w = wr[lane + i * 32];
        acc += a.x * w.x + a.y * w.y + a.z * w.z + a.w * w.w;
    }
#pragma unroll
    for (int off = 16; off > 0; off >>= 1)
        acc += __shfl_xor_sync(0xffffffffu, acc, off);
    if (lane == 0) g_qh[b * DD + e] = acc;
}

// ---------------------------------------------------------------------------
// Fused scores kernel (HMMA mma.sync), 2-term split:
//   kh = keys_h * (Wk_hi + Wk_lo)
// CTA = (b, 128-n tile). 8 e-passes of 128. Per pass 16 K-chunks of 64.
// Chunk = {A(keys_h), Bhi, Blo} staged once via cp.async double-buffer into
// XOR-swizzled smem (no pad). Both B segments accumulate into the same C.
// Epilogue: sacc += v*tanh(qh + C) in registers.
// ---------------------------------------------------------------------------
#define TILE_BYTES 16384                 // 128 x 64 halves
#define STAGE_BYTES (3 * TILE_BYTES)     // A + Bhi + Blo
#define OFF_QS (2 * STAGE_BYTES)         // 98304
#define OFF_VS (OFF_QS + 512)
#define OFF_RED (OFF_VS + 512)
#define SMEM_TOTAL (OFF_RED + 1024)

// swizzled byte offset inside a 128x(64 half) tile: row, 16B-group c8 (0..7)
__device__ __forceinline__ uint32_t swz(int row, int c8) {
    return (uint32_t)(row * 128 + ((c8 ^ (row & 7)) << 4));
}

__global__ __launch_bounds__(256, 2)
void scores_mma_kernel(const float* __restrict__ v) {
    extern __shared__ char sm[];
    const uint32_t sbase = smem_u32(sm);
    const int tid = threadIdx.x;
    const int wid = tid >> 5;
    const int lane = tid & 31;
    const int b = blockIdx.x;
    const int n0 = blockIdx.y * 128;

    const int wn = wid & 3;   // n-warp (0..3), 32 rows each
    const int we = wid >> 2;  // e-warp (0..1), 64 cols each

    float* qs = reinterpret_cast<float*>(sm + OFF_QS);
    float* vs = reinterpret_cast<float*>(sm + OFF_VS);
    float* red = reinterpret_cast<float*>(sm + OFF_RED);

    const __half* keyb = g_keys_hi + ((size_t)b * NN + n0) * DD;

    // staging indices: thread covers (row, c8) pairs
    const int st_row = tid >> 3;       // 0..31 (+32 steps)
    const int st_c8 = tid & 7;

    // ldmatrix lane addressing
    const int a_row = lane & 15;
    const int a_sel = lane >> 4;       // 16B group within k16 (0/1)
    const int b_g = lane & 7;
    const int b_sel = lane >> 3;
    const int b_row = b_g + ((b_sel >> 1) << 3);
    const int b_c8s = b_sel & 1;       // 16B group within k16

    float C[2][8][4];
#pragma unroll
    for (int m = 0; m < 2; m++)
#pragma unroll
        for (int nf = 0; nf < 8; nf++)
#pragma unroll
            for (int r = 0; r < 4; r++) C[m][nf][r] = 0.f;
    float sacc[4] = {0.f, 0.f, 0.f, 0.f};

    for (int ep = 0; ep < 8; ep++) {
        const int e0 = ep * 128;
        if (tid < 128) {
            qs[tid] = g_qh[b * DD + e0 + tid];
            vs[tid] = v[e0 + tid];
        }
        const __half* whi = g_wk_hi + (size_t)e0 * DD;
        const __half* wlo = g_wk_lo + (size_t)e0 * DD;

        auto stage = [&](int c) {
            const int k0 = c * 64;
            const uint32_t base = sbase + (uint32_t)(c & 1) * STAGE_BYTES;
#pragma unroll
            for (int it = 0; it < 4; it++) {
                int row = st_row + it * 32;
                uint32_t off = swz(row, st_c8);
                const size_t g = (size_t)row * DD + k0 + st_c8 * 8;
                cp_async16(base + off, keyb + g);
                cp_async16(base + TILE_BYTES + off, whi + g);
                cp_async16(base + 2 * TILE_BYTES + off, wlo + g);
            }
        };

        stage(0);
        cp_commit();

        for (int c = 0; c < 16; c++) {
            if (c < 15) {
                stage(c + 1);
                cp_commit();
                cp_wait<1>();
            } else {
                cp_wait<0>();
            }
            __syncthreads();

            const uint32_t bufA = sbase + (uint32_t)(c & 1) * STAGE_BYTES;

#pragma unroll
            for (int kk = 0; kk < 4; kk++) {
                uint32_t a[2][4];
#pragma unroll
                for (int m = 0; m < 2; m++) {
                    int row = wn * 32 + m * 16 + a_row;
                    ldsm4(a[m], bufA + swz(row, kk * 2 + a_sel));
                }
#pragma unroll
                for (int seg = 0; seg < 2; seg++) {
                    const uint32_t bufB = bufA + (1 + seg) * TILE_BYTES;
                    uint32_t bf[4][4];
#pragma unroll
                    for (int q = 0; q < 4; q++) {
                        int row = we * 64 + q * 16 + b_row;
                        ldsm4(bf[q], bufB + swz(row, kk * 2 + b_c8s));
                    }
#pragma unroll
                    for (int m = 0; m < 2; m++)
#pragma unroll
                        for (int nf = 0; nf < 8; nf++)
                            hmma(C[m][nf], a[m],
                                 bf[nf >> 1][(nf & 1) * 2],
                                 bf[nf >> 1][(nf & 1) * 2 + 1]);
                }
            }
            __syncthreads();
        }

        // epilogue: sacc += v * tanh(qh + C); zero C for next pass
#pragma unroll
        for (int m = 0; m < 2; m++)
#pragma unroll
            for (int nf = 0; nf < 8; nf++) {
                float* c = C[m][nf];
                int ec = we * 64 + nf * 8 + ((lane & 3) << 1);
                float q0 = qs[ec], q1 = qs[ec + 1];
                float v0 = vs[ec], v1 = vs[ec + 1];
                sacc[m * 2 + 0] += v0 * tanh_fast(q0 + c[0]) +
                                   v1 * tanh_fast(q1 + c[1]);
                sacc[m * 2 + 1] += v0 * tanh_fast(q0 + c[2]) +
                                   v1 * tanh_fast(q1 + c[3]);
                c[0] = c[1] = c[2] = c[3] = 0.f;
            }
        __syncthreads();   // qs/vs safe to overwrite next pass
    }

    // reduce sacc over the 4-lane k-groups (same rows)
#pragma unroll
    for (int i = 0; i < 4; i++) {
        sacc[i] += __shfl_xor_sync(0xffffffffu, sacc[i], 1);
        sacc[i] += __shfl_xor_sync(0xffffffffu, sacc[i], 2);
    }
    if ((lane & 3) == 0) {
        int g = lane >> 2;
        float* r = red + we * 128 + wn * 32;
        r[g]      = sacc[0];
        r[g + 8]  = sacc[1];
        r[g + 16] = sacc[2];
        r[g + 24] = sacc[3];
    }
    __syncthreads();
    if (tid < 128)
        g_scores[b * NN + n0 + tid] = red[tid] + red[128 + tid];
}

// ---------------------------------------------------------------------------
// softmax over N per row; writes alpha into d_out[B*D ...]
// ---------------------------------------------------------------------------
__global__ void softmax_kernel(float* __restrict__ out) {
    __shared__ float sx[NN];
    __shared__ float red[256];
    const int b = blockIdx.x;
    const int tid = threadIdx.x;
    const float* s = &g_scores[b * NN];

    float m = -1e30f;
    for (int i = tid; i < NN; i += 256) {
        float val = s[i];
        sx[i] = val;
        m = fmaxf(m, val);
    }
    red[tid] = m;
    __syncthreads();
    for (int off = 128; off > 0; off >>= 1) {
        if (tid < off) red[tid] = fmaxf(red[tid], red[tid + off]);
        __syncthreads();
    }
    const float M = red[0];
    __syncthreads();

    float sum = 0.f;
    for (int i = tid; i < NN; i += 256) {
        float e = __expf(sx[i] - M);
        sx[i] = e;
        sum += e;
    }
    red[tid] = sum;
    __syncthreads();
    for (int off = 128; off > 0; off >>= 1) {
        if (tid < off) red[tid] += red[tid + off];
        __syncthreads();
    }
    const float inv = 1.f / red[0];
    __syncthreads();

    float* alpha = out + (size_t)BB * DD + (size_t)b * NN;
    for (int i = tid; i < NN; i += 256)
        alpha[i] = sx[i] * inv;
}

// ---------------------------------------------------------------------------
// context[b,d] = sum_n alpha[b,n] * keys[b,n,d]
// grid (B, 4): 256 CTAs; thread per d element; unrolled n for MLP.
// ---------------------------------------------------------------------------
__global__ void context_kernel(const float* __restrict__ keys,
                               float* __restrict__ out) {
    __shared__ float al[NN];
    const int b = blockIdx.x;
    const int d = blockIdx.y * 256 + threadIdx.x;
    const float* alpha = out + (size_t)BB * DD + (size_t)b * NN;
    for (int i = threadIdx.x; i < NN; i += 256) al[i] = alpha[i];
    __syncthreads();

    const float* kb = keys + (size_t)b * NN * DD + d;
    float acc0 = 0.f, acc1 = 0.f, acc2 = 0.f, acc3 = 0.f;
#pragma unroll 4
    for (int n = 0; n < NN; n += 4) {
        acc0 += al[n + 0] * kb[(size_t)(n + 0) * DD];
        acc1 += al[n + 1] * kb[(size_t)(n + 1) * DD];
        acc2 += al[n + 2] * kb[(size_t)(n + 2) * DD];
        acc3 += al[n + 3] * kb[(size_t)(n + 3) * DD];
    }
    out[(size_t)b * DD + d] = (acc0 + acc1) + (acc2 + acc3);
}

// ---------------------------------------------------------------------------
extern "C" void kernel_launch(void* const* d_in, const int* in_sizes, int n_in,
                              void* d_out, int out_size) {
    const float* h_t  = (const float*)d_in[0];
    const float* keys = (const float*)d_in[1];
    const float* W_h  = (const float*)d_in[2];
    const float* W_k  = (const float*)d_in[3];
    const float* v    = (const float*)d_in[4];
    float* out = (float*)d_out;

    cudaFuncSetAttribute(scores_mma_kernel,
                         cudaFuncAttributeMaxDynamicSharedMemorySize, SMEM_TOTAL);

    __half *khi, *whi, *wlo;
    cudaGetSymbolAddress((void**)&khi, g_keys_hi);
    cudaGetSymbolAddress((void**)&whi, g_wk_hi);
    cudaGetSymbolAddress((void**)&wlo, g_wk_lo);

    split1_kernel<<<(size_t)BB * NN * DD / 4 / 256, 256>>>(keys, khi);
    split2_kernel<<<DD * DD / 4 / 256, 256>>>(W_k, whi, wlo);
    qh_kernel<<<dim3(BB, DD / 8), 256>>>(h_t, W_h);
    scores_mma_kernel<<<dim3(BB, 8), 256, SMEM_TOTAL>>>(v);
    softmax_kernel<<<BB, 256>>>(out);
    context_kernel<<<dim3(BB, 4), 256>>>(keys, out);
}